// round 2
// baseline (speedup 1.0000x reference)
#include <cuda_runtime.h>
#include <math.h>

#define NN 50000
#define NE 800000
#define F 128
#define HEADS 4
#define HD 32
#define NG 64

// ---------------- static device scratch (no allocs allowed) ----------------
__device__ __align__(16) float g_h[NN * F];
__device__ __align__(16) float g_xl[NN * F];
__device__ __align__(16) float g_xr[NN * F];
__device__ __align__(16) float g_agg[NN * F];
__device__ __align__(16) float g_logits[NE * HEADS];   // reused: logits -> exp
__device__ __align__(16) float g_segmax[NN * HEADS];
__device__ __align__(16) float g_denom[NN * HEADS];
__device__ __align__(16) float g_pool[NG * F];
__device__ float g_cnt[NG];

// int32-normalized indices (inputs may arrive as int32 or int64)
__device__ int g_ei32[2 * NE];
__device__ int g_batch32[NN];
__device__ int g_is64;

// ---------------- dtype sniff: int64 buffers have all-zero odd 32b words ----
__global__ void sniff_dtype(const void* ei) {
    __shared__ int nz;
    if (threadIdx.x == 0) nz = 0;
    __syncthreads();
    const int* p = (const int*)ei;
    // sample odd 32-bit words 1,3,...,2047 (well within buffer either way)
    if (p[2 * threadIdx.x + 1] != 0) atomicOr(&nz, 1);
    __syncthreads();
    if (threadIdx.x == 0) g_is64 = (nz == 0) ? 1 : 0;
}

__global__ void convert_idx(const void* src, int* dst, int n) {
    int i = blockIdx.x * blockDim.x + threadIdx.x;
    if (i >= n) return;
    if (g_is64) dst[i] = (int)((const long long*)src)[i];
    else        dst[i] = ((const int*)src)[i];
}

// float atomic max via int/uint ordering trick (valid for all floats incl -inf)
__device__ __forceinline__ void atomicMaxF(float* addr, float val) {
    if (val >= 0.0f) atomicMax((int*)addr, __float_as_int(val));
    else             atomicMin((unsigned int*)addr, __float_as_uint(val));
}

// ---------------- GEMM: out[n,128] = in[n,128] @ W[128,128] + b ----------------
// block = 256 threads, tile = 64 rows x 128 cols, 8x4 register micro-tile.
__global__ void gemm_bias(const float* __restrict__ A, const float* __restrict__ W,
                          const float* __restrict__ bias, float* __restrict__ out,
                          int n) {
    __shared__ __align__(16) float As[64 * 132];  // padded rows kill bank conflicts
    int row0 = blockIdx.x * 64;

    for (int i = threadIdx.x; i < 64 * 32; i += 256) {
        int r = i >> 5, c = i & 31;
        float4 v = make_float4(0.f, 0.f, 0.f, 0.f);
        if (row0 + r < n) v = *(const float4*)&A[(size_t)(row0 + r) * F + c * 4];
        *(float4*)&As[r * 132 + c * 4] = v;
    }
    __syncthreads();

    int tr = threadIdx.x >> 5;   // 0..7  (row group)
    int tc = threadIdx.x & 31;   // 0..31 (col group of 4)
    float acc[8][4];
#pragma unroll
    for (int i = 0; i < 8; i++)
#pragma unroll
        for (int j = 0; j < 4; j++) acc[i][j] = 0.f;

#pragma unroll 4
    for (int k = 0; k < 128; k++) {
        float4 b = __ldg((const float4*)&W[k * F + tc * 4]);  // L1-resident (64KB)
#pragma unroll
        for (int i = 0; i < 8; i++) {
            float a = As[(tr * 8 + i) * 132 + k];             // smem broadcast
            acc[i][0] += a * b.x;
            acc[i][1] += a * b.y;
            acc[i][2] += a * b.z;
            acc[i][3] += a * b.w;
        }
    }
    float4 bb = __ldg((const float4*)&bias[tc * 4]);
#pragma unroll
    for (int i = 0; i < 8; i++) {
        int r = row0 + tr * 8 + i;
        if (r < n) {
            float4 o;
            o.x = acc[i][0] + bb.x;
            o.y = acc[i][1] + bb.y;
            o.z = acc[i][2] + bb.z;
            o.w = acc[i][3] + bb.w;
            *(float4*)&out[(size_t)r * F + tc * 4] = o;
        }
    }
}

// ---------------- per-layer init ----------------
__global__ void layer_init() {
    int i = blockIdx.x * blockDim.x + threadIdx.x;
    if (i < NN * F) g_agg[i] = 0.f;
    if (i < NN * HEADS) {
        g_segmax[i] = __int_as_float(0xff800000);  // -inf
        g_denom[i] = 0.f;
    }
}

// ---------------- pass A: logits + segment max (warp per edge) ----------------
__global__ void edge_logits(const float* __restrict__ att) {
    int warp = (blockIdx.x * blockDim.x + threadIdx.x) >> 5;
    int lane = threadIdx.x & 31;
    if (warp >= NE) return;
    int src = g_ei32[warp];
    int dst = g_ei32[NE + warp];
    float t[HEADS];
#pragma unroll
    for (int h = 0; h < HEADS; h++) {
        float v = g_xl[(size_t)src * F + h * HD + lane] +
                  g_xr[(size_t)dst * F + h * HD + lane];
        v = (v > 0.f) ? v : 0.2f * v;  // leaky_relu
        t[h] = v * __ldg(&att[h * HD + lane]);
    }
#pragma unroll
    for (int off = 16; off; off >>= 1) {
#pragma unroll
        for (int h = 0; h < HEADS; h++)
            t[h] += __shfl_xor_sync(0xffffffffu, t[h], off);
    }
    if (lane < HEADS) {
        float L = t[lane];
        g_logits[(size_t)warp * HEADS + lane] = L;
        atomicMaxF(&g_segmax[dst * HEADS + lane], L);
    }
}

// ---------------- pass B: exp + denom (thread per edge) ----------------
__global__ void edge_exp() {
    int e = blockIdx.x * blockDim.x + threadIdx.x;
    if (e >= NE) return;
    int dst = g_ei32[NE + e];
    float4 lg = *(const float4*)&g_logits[(size_t)e * 4];
    float4 mx = *(const float4*)&g_segmax[dst * 4];
    float4 ex;
    ex.x = expf(lg.x - mx.x);
    ex.y = expf(lg.y - mx.y);
    ex.z = expf(lg.z - mx.z);
    ex.w = expf(lg.w - mx.w);
    *(float4*)&g_logits[(size_t)e * 4] = ex;
    atomicAdd(&g_denom[dst * 4 + 0], ex.x);
    atomicAdd(&g_denom[dst * 4 + 1], ex.y);
    atomicAdd(&g_denom[dst * 4 + 2], ex.z);
    atomicAdd(&g_denom[dst * 4 + 3], ex.w);
}

// ---------------- pass C: scatter messages (warp per edge) ----------------
__global__ void edge_scatter() {
    int warp = (blockIdx.x * blockDim.x + threadIdx.x) >> 5;
    int lane = threadIdx.x & 31;
    if (warp >= NE) return;
    int src = g_ei32[warp];
    int dst = g_ei32[NE + warp];
    float a[HEADS];
#pragma unroll
    for (int h = 0; h < HEADS; h++)
        a[h] = g_logits[(size_t)warp * HEADS + h] /
               (g_denom[dst * HEADS + h] + 1e-16f);
#pragma unroll
    for (int h = 0; h < HEADS; h++)
        atomicAdd(&g_agg[(size_t)dst * F + h * HD + lane],
                  a[h] * g_xl[(size_t)src * F + h * HD + lane]);
}

// ---------------- node epilogue: +bias, ELU, +res, LayerNorm (warp per node) ----
__global__ void node_epilogue(const float* __restrict__ conv_b,
                              const float* __restrict__ ln_g,
                              const float* __restrict__ ln_b) {
    int node = (blockIdx.x * blockDim.x + threadIdx.x) >> 5;
    int lane = threadIdx.x & 31;
    if (node >= NN) return;
    float v[HEADS];
#pragma unroll
    for (int h = 0; h < HEADS; h++) {
        float t = g_agg[(size_t)node * F + h * HD + lane] + __ldg(&conv_b[h * HD + lane]);
        t = (t > 0.f) ? t : expm1f(t);  // elu
        v[h] = t + g_h[(size_t)node * F + h * HD + lane];  // residual
    }
    float s = v[0] + v[1] + v[2] + v[3];
#pragma unroll
    for (int off = 16; off; off >>= 1) s += __shfl_xor_sync(0xffffffffu, s, off);
    float mu = s * (1.f / 128.f);
    float d[HEADS];
    float sq = 0.f;
#pragma unroll
    for (int h = 0; h < HEADS; h++) {
        d[h] = v[h] - mu;
        sq += d[h] * d[h];
    }
#pragma unroll
    for (int off = 16; off; off >>= 1) sq += __shfl_xor_sync(0xffffffffu, sq, off);
    float rstd = rsqrtf(sq * (1.f / 128.f) + 1e-5f);
#pragma unroll
    for (int h = 0; h < HEADS; h++)
        g_h[(size_t)node * F + h * HD + lane] =
            d[h] * rstd * __ldg(&ln_g[h * HD + lane]) + __ldg(&ln_b[h * HD + lane]);
}

// ---------------- pooling ----------------
__global__ void pool_zero() {
    int i = blockIdx.x * blockDim.x + threadIdx.x;
    if (i < NG * F) g_pool[i] = 0.f;
    if (i < NG) g_cnt[i] = 0.f;
}

__global__ void pool_accum() {
    int node = (blockIdx.x * blockDim.x + threadIdx.x) >> 5;
    int lane = threadIdx.x & 31;
    if (node >= NN) return;
    int g = g_batch32[node];
#pragma unroll
    for (int h = 0; h < HEADS; h++)
        atomicAdd(&g_pool[g * F + h * HD + lane],
                  g_h[(size_t)node * F + h * HD + lane]);
    if (lane == 0) atomicAdd(&g_cnt[g], 1.0f);
}

__global__ void pool_final(float* __restrict__ out) {
    int i = blockIdx.x * blockDim.x + threadIdx.x;
    if (i >= NG * F) return;
    out[i] = g_pool[i] / fmaxf(g_cnt[i >> 7], 1.0f);
}

// ---------------- launch ----------------
extern "C" void kernel_launch(void* const* d_in, const int* in_sizes, int n_in,
                              void* d_out, int out_size) {
    const float* x        = (const float*)d_in[0];
    const void*  ei_raw   = d_in[1];
    const void*  batch_raw= d_in[2];
    const float* emb_W    = (const float*)d_in[3];
    const float* emb_b    = (const float*)d_in[4];
    const float* lin_l_W  = (const float*)d_in[5];
    const float* lin_l_b  = (const float*)d_in[6];
    const float* lin_r_W  = (const float*)d_in[7];
    const float* lin_r_b  = (const float*)d_in[8];
    const float* att      = (const float*)d_in[9];
    const float* conv_b   = (const float*)d_in[10];
    const float* ln_g     = (const float*)d_in[11];
    const float* ln_b     = (const float*)d_in[12];
    float* out = (float*)d_out;

    float *p_h, *p_xl, *p_xr;
    int *p_ei, *p_batch;
    cudaGetSymbolAddress((void**)&p_h, g_h);
    cudaGetSymbolAddress((void**)&p_xl, g_xl);
    cudaGetSymbolAddress((void**)&p_xr, g_xr);
    cudaGetSymbolAddress((void**)&p_ei, g_ei32);
    cudaGetSymbolAddress((void**)&p_batch, g_batch32);

    const int GEMM_GRID = (NN + 63) / 64;       // 782
    const int INIT_GRID = (NN * F + 255) / 256; // 25000
    const int EW_GRID   = (NE + 7) / 8;         // warp-per-edge, 8 warps/block
    const int ET_GRID   = (NE + 255) / 256;     // thread-per-edge
    const int NW_GRID   = (NN + 7) / 8;         // warp-per-node

    // normalize index dtypes (int64 vs int32) into int32 scratch
    sniff_dtype<<<1, 1024>>>(ei_raw);
    convert_idx<<<(2 * NE + 255) / 256, 256>>>(ei_raw, p_ei, 2 * NE);
    convert_idx<<<(NN + 255) / 256, 256>>>(batch_raw, p_batch, NN);

    // embedding
    gemm_bias<<<GEMM_GRID, 256>>>(x, emb_W, emb_b, p_h, NN);

    for (int l = 0; l < 3; l++) {
        const float* Wl = lin_l_W + (size_t)l * F * F;
        const float* bl = lin_l_b + (size_t)l * F;
        const float* Wr = lin_r_W + (size_t)l * F * F;
        const float* br = lin_r_b + (size_t)l * F;
        const float* at = att + (size_t)l * F;      // [4,32]
        const float* cb = conv_b + (size_t)l * F;
        const float* lg = ln_g + (size_t)l * F;
        const float* lb = ln_b + (size_t)l * F;

        gemm_bias<<<GEMM_GRID, 256>>>(p_h, Wl, bl, p_xl, NN);
        gemm_bias<<<GEMM_GRID, 256>>>(p_h, Wr, br, p_xr, NN);
        layer_init<<<INIT_GRID, 256>>>();
        edge_logits<<<EW_GRID, 256>>>(at);
        edge_exp<<<ET_GRID, 256>>>();
        edge_scatter<<<EW_GRID, 256>>>();
        node_epilogue<<<NW_GRID, 256>>>(cb, lg, lb);
    }

    pool_zero<<<(NG * F + 255) / 256, 256>>>();
    pool_accum<<<NW_GRID, 256>>>();
    pool_final<<<(NG * F + 255) / 256, 256>>>(out);
}

// round 3
// speedup vs baseline: 2.1189x; 2.1189x over previous
#include <cuda_runtime.h>
#include <math.h>

#define NN 50000
#define NE 800000
#define F 128
#define HEADS 4
#define HD 32
#define NG 64

// ---------------- static device scratch ----------------
__device__ __align__(16) float g_h[NN * F];
__device__ __align__(16) float g_xl[NN * F];
__device__ __align__(16) float g_xr[NN * F];
__device__ __align__(16) float g_pool[NG * F];
__device__ float g_cnt[NG];

__device__ int g_ei32[2 * NE];
__device__ int g_batch32[NN];
__device__ int g_is64;

// CSR by destination (graph is identical across layers -> build once)
__device__ int g_deg[NN];
__device__ int g_rowptr[NN + 1];
__device__ int g_cursor[NN];
__device__ int g_csrsrc[NE];

// ---------------- dtype sniff: int64 buffers have all-zero odd 32b words ----
__global__ void sniff_dtype(const void* ei) {
    __shared__ int nz;
    if (threadIdx.x == 0) nz = 0;
    __syncthreads();
    const int* p = (const int*)ei;
    if (p[2 * threadIdx.x + 1] != 0) atomicOr(&nz, 1);
    __syncthreads();
    if (threadIdx.x == 0) g_is64 = (nz == 0) ? 1 : 0;
}

__global__ void convert_idx(const void* src, int* dst, int n) {
    int i = blockIdx.x * blockDim.x + threadIdx.x;
    if (i >= n) return;
    if (g_is64) dst[i] = (int)((const long long*)src)[i];
    else        dst[i] = ((const int*)src)[i];
}

// ---------------- CSR build ----------------
__global__ void csr_count_zero() {
    int i = blockIdx.x * blockDim.x + threadIdx.x;
    if (i < NN) g_deg[i] = 0;
}

__global__ void csr_count() {
    int e = blockIdx.x * blockDim.x + threadIdx.x;
    if (e >= NE) return;
    atomicAdd(&g_deg[g_ei32[NE + e]], 1);
}

// single-block scan over NN degrees -> exclusive prefix in g_rowptr (+ cursor copy)
__global__ void csr_scan() {
    __shared__ int wsum[32];
    __shared__ int carry_s;
    int tid = threadIdx.x, lane = tid & 31, wid = tid >> 5;
    if (tid == 0) carry_s = 0;
    __syncthreads();
    for (int base = 0; base < NN; base += 1024) {
        int i = base + tid;
        int v = (i < NN) ? g_deg[i] : 0;
        int x = v;
#pragma unroll
        for (int off = 1; off < 32; off <<= 1) {
            int y = __shfl_up_sync(0xffffffffu, x, off);
            if (lane >= off) x += y;
        }
        if (lane == 31) wsum[wid] = x;
        __syncthreads();
        if (wid == 0) {
            int y = wsum[lane];
#pragma unroll
            for (int off = 1; off < 32; off <<= 1) {
                int z = __shfl_up_sync(0xffffffffu, y, off);
                if (lane >= off) y += z;
            }
            wsum[lane] = y;
        }
        __syncthreads();
        int carry = carry_s;
        int excl = x - v + (wid > 0 ? wsum[wid - 1] : 0) + carry;
        if (i < NN) { g_rowptr[i] = excl; g_cursor[i] = excl; }
        int total = wsum[31];
        __syncthreads();
        if (tid == 0) carry_s = carry + total;
        __syncthreads();
    }
    if (threadIdx.x == 0) g_rowptr[NN] = carry_s;
}

__global__ void csr_fill() {
    int e = blockIdx.x * blockDim.x + threadIdx.x;
    if (e >= NE) return;
    int src = g_ei32[e];
    int dst = g_ei32[NE + e];
    int pos = atomicAdd(&g_cursor[dst], 1);
    g_csrsrc[pos] = src;
}

// ---------------- GEMM: out[n,128] = in[n,128] @ W[128,128] + b ----------------
__global__ void gemm_bias(const float* __restrict__ A, const float* __restrict__ W,
                          const float* __restrict__ bias, float* __restrict__ out,
                          int n) {
    __shared__ __align__(16) float As[64 * 132];
    int row0 = blockIdx.x * 64;

    for (int i = threadIdx.x; i < 64 * 32; i += 256) {
        int r = i >> 5, c = i & 31;
        float4 v = make_float4(0.f, 0.f, 0.f, 0.f);
        if (row0 + r < n) v = *(const float4*)&A[(size_t)(row0 + r) * F + c * 4];
        *(float4*)&As[r * 132 + c * 4] = v;
    }
    __syncthreads();

    int tr = threadIdx.x >> 5;
    int tc = threadIdx.x & 31;
    float acc[8][4];
#pragma unroll
    for (int i = 0; i < 8; i++)
#pragma unroll
        for (int j = 0; j < 4; j++) acc[i][j] = 0.f;

#pragma unroll 4
    for (int k = 0; k < 128; k++) {
        float4 b = __ldg((const float4*)&W[k * F + tc * 4]);
#pragma unroll
        for (int i = 0; i < 8; i++) {
            float a = As[(tr * 8 + i) * 132 + k];
            acc[i][0] += a * b.x;
            acc[i][1] += a * b.y;
            acc[i][2] += a * b.z;
            acc[i][3] += a * b.w;
        }
    }
    float4 bb = __ldg((const float4*)&bias[tc * 4]);
#pragma unroll
    for (int i = 0; i < 8; i++) {
        int r = row0 + tr * 8 + i;
        if (r < n) {
            float4 o;
            o.x = acc[i][0] + bb.x;
            o.y = acc[i][1] + bb.y;
            o.z = acc[i][2] + bb.z;
            o.w = acc[i][3] + bb.w;
            *(float4*)&out[(size_t)r * F + tc * 4] = o;
        }
    }
}

// ---------------- fused gather: softmax-attention aggregate + epilogue ----------
// warp per dst node; lane owns features [4*lane, 4*lane+4)  (head = lane>>3)
__device__ __forceinline__ float lrelu(float v) {
    return (v > 0.f) ? v : 0.2f * v;
}

__device__ __forceinline__ void proc_edge(float4 xl4, const float4& xr4,
                                          const float4& attv, int lane,
                                          float& d, float4& s) {
    float p = lrelu(xl4.x + xr4.x) * attv.x
            + lrelu(xl4.y + xr4.y) * attv.y
            + lrelu(xl4.z + xr4.z) * attv.z
            + lrelu(xl4.w + xr4.w) * attv.w;
    p += __shfl_xor_sync(0xffffffffu, p, 1);
    p += __shfl_xor_sync(0xffffffffu, p, 2);
    p += __shfl_xor_sync(0xffffffffu, p, 4);
    // one exp per octet, broadcast (logits are O(1); softmax shift-invariant)
    float w = 0.f;
    if ((lane & 7) == 0) w = __expf(p);
    w = __shfl_sync(0xffffffffu, w, lane & 24);
    d += w;
    s.x += w * xl4.x;
    s.y += w * xl4.y;
    s.z += w * xl4.z;
    s.w += w * xl4.w;
}

__global__ void __launch_bounds__(256) gat_gather(
        const float* __restrict__ att, const float* __restrict__ conv_b,
        const float* __restrict__ ln_g, const float* __restrict__ ln_b) {
    int node = (blockIdx.x * blockDim.x + threadIdx.x) >> 5;
    int lane = threadIdx.x & 31;
    if (node >= NN) return;
    int beg = g_rowptr[node];
    int end = g_rowptr[node + 1];

    float4 xr4 = *(const float4*)&g_xr[(size_t)node * F + lane * 4];
    float4 attv = __ldg((const float4*)&att[lane * 4]);

    float d = 0.f;
    float4 s = make_float4(0.f, 0.f, 0.f, 0.f);

    int e = beg;
    for (; e + 4 <= end; e += 4) {
        int s0 = g_csrsrc[e + 0];
        int s1 = g_csrsrc[e + 1];
        int s2 = g_csrsrc[e + 2];
        int s3 = g_csrsrc[e + 3];
        float4 a0 = __ldg((const float4*)&g_xl[(size_t)s0 * F + lane * 4]);
        float4 a1 = __ldg((const float4*)&g_xl[(size_t)s1 * F + lane * 4]);
        float4 a2 = __ldg((const float4*)&g_xl[(size_t)s2 * F + lane * 4]);
        float4 a3 = __ldg((const float4*)&g_xl[(size_t)s3 * F + lane * 4]);
        proc_edge(a0, xr4, attv, lane, d, s);
        proc_edge(a1, xr4, attv, lane, d, s);
        proc_edge(a2, xr4, attv, lane, d, s);
        proc_edge(a3, xr4, attv, lane, d, s);
    }
    for (; e < end; e++) {
        int s0 = g_csrsrc[e];
        float4 a0 = __ldg((const float4*)&g_xl[(size_t)s0 * F + lane * 4]);
        proc_edge(a0, xr4, attv, lane, d, s);
    }

    // epilogue: msg/denom + conv bias, ELU, residual, LayerNorm
    float invd = 1.0f / (d + 1e-16f);
    float4 cb = __ldg((const float4*)&conv_b[lane * 4]);
    float4 o;
    o.x = s.x * invd + cb.x;
    o.y = s.y * invd + cb.y;
    o.z = s.z * invd + cb.z;
    o.w = s.w * invd + cb.w;
    o.x = (o.x > 0.f) ? o.x : (__expf(o.x) - 1.f);
    o.y = (o.y > 0.f) ? o.y : (__expf(o.y) - 1.f);
    o.z = (o.z > 0.f) ? o.z : (__expf(o.z) - 1.f);
    o.w = (o.w > 0.f) ? o.w : (__expf(o.w) - 1.f);
    float4 res = *(const float4*)&g_h[(size_t)node * F + lane * 4];
    o.x += res.x; o.y += res.y; o.z += res.z; o.w += res.w;

    float sum = o.x + o.y + o.z + o.w;
#pragma unroll
    for (int off = 16; off; off >>= 1) sum += __shfl_xor_sync(0xffffffffu, sum, off);
    float mu = sum * (1.f / 128.f);
    float dx0 = o.x - mu, dx1 = o.y - mu, dx2 = o.z - mu, dx3 = o.w - mu;
    float sq = dx0 * dx0 + dx1 * dx1 + dx2 * dx2 + dx3 * dx3;
#pragma unroll
    for (int off = 16; off; off >>= 1) sq += __shfl_xor_sync(0xffffffffu, sq, off);
    float rstd = rsqrtf(sq * (1.f / 128.f) + 1e-5f);

    float4 lg = __ldg((const float4*)&ln_g[lane * 4]);
    float4 lb = __ldg((const float4*)&ln_b[lane * 4]);
    float4 w;
    w.x = dx0 * rstd * lg.x + lb.x;
    w.y = dx1 * rstd * lg.y + lb.y;
    w.z = dx2 * rstd * lg.z + lb.z;
    w.w = dx3 * rstd * lg.w + lb.w;
    *(float4*)&g_h[(size_t)node * F + lane * 4] = w;
}

// ---------------- pooling ----------------
__global__ void pool_zero() {
    int i = blockIdx.x * blockDim.x + threadIdx.x;
    if (i < NG * F) g_pool[i] = 0.f;
    if (i < NG) g_cnt[i] = 0.f;
}

__global__ void pool_accum() {
    int node = (blockIdx.x * blockDim.x + threadIdx.x) >> 5;
    int lane = threadIdx.x & 31;
    if (node >= NN) return;
    int g = g_batch32[node];
#pragma unroll
    for (int h = 0; h < HEADS; h++)
        atomicAdd(&g_pool[g * F + h * HD + lane],
                  g_h[(size_t)node * F + h * HD + lane]);
    if (lane == 0) atomicAdd(&g_cnt[g], 1.0f);
}

__global__ void pool_final(float* __restrict__ out) {
    int i = blockIdx.x * blockDim.x + threadIdx.x;
    if (i >= NG * F) return;
    out[i] = g_pool[i] / fmaxf(g_cnt[i >> 7], 1.0f);
}

// ---------------- launch ----------------
extern "C" void kernel_launch(void* const* d_in, const int* in_sizes, int n_in,
                              void* d_out, int out_size) {
    const float* x        = (const float*)d_in[0];
    const void*  ei_raw   = d_in[1];
    const void*  batch_raw= d_in[2];
    const float* emb_W    = (const float*)d_in[3];
    const float* emb_b    = (const float*)d_in[4];
    const float* lin_l_W  = (const float*)d_in[5];
    const float* lin_l_b  = (const float*)d_in[6];
    const float* lin_r_W  = (const float*)d_in[7];
    const float* lin_r_b  = (const float*)d_in[8];
    const float* att      = (const float*)d_in[9];
    const float* conv_b   = (const float*)d_in[10];
    const float* ln_g     = (const float*)d_in[11];
    const float* ln_b     = (const float*)d_in[12];
    float* out = (float*)d_out;

    float *p_h, *p_xl, *p_xr;
    int *p_ei, *p_batch;
    cudaGetSymbolAddress((void**)&p_h, g_h);
    cudaGetSymbolAddress((void**)&p_xl, g_xl);
    cudaGetSymbolAddress((void**)&p_xr, g_xr);
    cudaGetSymbolAddress((void**)&p_ei, g_ei32);
    cudaGetSymbolAddress((void**)&p_batch, g_batch32);

    const int GEMM_GRID = (NN + 63) / 64;
    const int ET_GRID   = (NE + 255) / 256;
    const int NW_GRID   = (NN + 7) / 8;

    // normalize index dtypes, then build dst-CSR once
    sniff_dtype<<<1, 1024>>>(ei_raw);
    convert_idx<<<(2 * NE + 255) / 256, 256>>>(ei_raw, p_ei, 2 * NE);
    convert_idx<<<(NN + 255) / 256, 256>>>(batch_raw, p_batch, NN);
    csr_count_zero<<<(NN + 255) / 256, 256>>>();
    csr_count<<<ET_GRID, 256>>>();
    csr_scan<<<1, 1024>>>();
    csr_fill<<<ET_GRID, 256>>>();

    // embedding
    gemm_bias<<<GEMM_GRID, 256>>>(x, emb_W, emb_b, p_h, NN);

    for (int l = 0; l < 3; l++) {
        gemm_bias<<<GEMM_GRID, 256>>>(p_h, lin_l_W + (size_t)l * F * F,
                                      lin_l_b + (size_t)l * F, p_xl, NN);
        gemm_bias<<<GEMM_GRID, 256>>>(p_h, lin_r_W + (size_t)l * F * F,
                                      lin_r_b + (size_t)l * F, p_xr, NN);
        gat_gather<<<NW_GRID, 256>>>(att + (size_t)l * F,
                                     conv_b + (size_t)l * F,
                                     ln_g + (size_t)l * F,
                                     ln_b + (size_t)l * F);
    }

    pool_zero<<<(NG * F + 255) / 256, 256>>>();
    pool_accum<<<NW_GRID, 256>>>();
    pool_final<<<(NG * F + 255) / 256, 256>>>(out);
}

// round 5
// speedup vs baseline: 2.4456x; 1.1541x over previous
#include <cuda_runtime.h>
#include <cuda_bf16.h>
#include <math.h>
#include <stdint.h>

#define NN 50000
#define NE 800000
#define F 128
#define HEADS 4
#define HD 32
#define NG 64
#define TILES ((NN + 127) / 128)   // 391
#define SAS 136                    // smem row stride in bf16 elems (272B: bank-safe)
#define SMEMSZ (4 * 128 * SAS * 2) // 139264 bytes

// ---------------- static device scratch ----------------
__device__ __align__(16) float g_h[NN * F];
__device__ __align__(16) float g_xl[NN * F];
__device__ __align__(16) float g_xr[NN * F];
__device__ __align__(16) float g_pool[NG * F];
__device__ float g_cnt[NG];

__device__ int g_ei32[2 * NE];
__device__ int g_batch32[NN];
__device__ int g_is64;

// CSR by destination
__device__ int g_deg[NN];
__device__ int g_rowptr[NN + 1];
__device__ int g_cursor[NN];
__device__ int g_csrsrc[NE];

// 7 weight matrices bf16 hi/lo, transposed to [n][k] row-major:
// 0=emb, 1..3=lin_l, 4..6=lin_r
__device__ __align__(16) __nv_bfloat16 g_Whi[7 * 16384];
__device__ __align__(16) __nv_bfloat16 g_Wlo[7 * 16384];

// ---------------- dtype sniff + index convert ----------------
__global__ void sniff_dtype(const void* ei) {
    __shared__ int nz;
    if (threadIdx.x == 0) nz = 0;
    __syncthreads();
    const int* p = (const int*)ei;
    if (p[2 * threadIdx.x + 1] != 0) atomicOr(&nz, 1);
    __syncthreads();
    if (threadIdx.x == 0) g_is64 = (nz == 0) ? 1 : 0;
}

__global__ void convert_idx(const void* src, int* dst, int n) {
    int i = blockIdx.x * blockDim.x + threadIdx.x;
    if (i >= n) return;
    if (g_is64) dst[i] = (int)((const long long*)src)[i];
    else        dst[i] = ((const int*)src)[i];
}

// ---------------- CSR build ----------------
__global__ void csr_count_zero() {
    int i = blockIdx.x * blockDim.x + threadIdx.x;
    if (i < NN) g_deg[i] = 0;
}

__global__ void csr_count() {
    int e = blockIdx.x * blockDim.x + threadIdx.x;
    if (e >= NE) return;
    atomicAdd(&g_deg[g_ei32[NE + e]], 1);
}

__global__ void csr_scan() {
    __shared__ int wsum[32];
    __shared__ int carry_s;
    int tid = threadIdx.x, lane = tid & 31, wid = tid >> 5;
    if (tid == 0) carry_s = 0;
    __syncthreads();
    for (int base = 0; base < NN; base += 1024) {
        int i = base + tid;
        int v = (i < NN) ? g_deg[i] : 0;
        int x = v;
#pragma unroll
        for (int off = 1; off < 32; off <<= 1) {
            int y = __shfl_up_sync(0xffffffffu, x, off);
            if (lane >= off) x += y;
        }
        if (lane == 31) wsum[wid] = x;
        __syncthreads();
        if (wid == 0) {
            int y = wsum[lane];
#pragma unroll
            for (int off = 1; off < 32; off <<= 1) {
                int z = __shfl_up_sync(0xffffffffu, y, off);
                if (lane >= off) y += z;
            }
            wsum[lane] = y;
        }
        __syncthreads();
        int carry = carry_s;
        int excl = x - v + (wid > 0 ? wsum[wid - 1] : 0) + carry;
        if (i < NN) { g_rowptr[i] = excl; g_cursor[i] = excl; }
        int total = wsum[31];
        __syncthreads();
        if (tid == 0) carry_s = carry + total;
        __syncthreads();
    }
    if (threadIdx.x == 0) g_rowptr[NN] = carry_s;
}

__global__ void csr_fill() {
    int e = blockIdx.x * blockDim.x + threadIdx.x;
    if (e >= NE) return;
    int src = g_ei32[e];
    int dst = g_ei32[NE + e];
    int pos = atomicAdd(&g_cursor[dst], 1);
    g_csrsrc[pos] = src;
}

// ---------------- bf16 split of W (transposed to [n][k]) --------------------
__global__ void split_W_all(const float* __restrict__ emb_W,
                            const float* __restrict__ llW,
                            const float* __restrict__ lrW) {
    int idx = blockIdx.x * blockDim.x + threadIdx.x;
    if (idx >= 7 * 16384) return;
    int w = idx >> 14, e = idx & 16383;
    int nrow = e >> 7, k = e & 127;
    float v;
    if (w == 0)      v = emb_W[k * F + nrow];
    else if (w < 4)  v = llW[(size_t)(w - 1) * F * F + k * F + nrow];
    else             v = lrW[(size_t)(w - 4) * F * F + k * F + nrow];
    __nv_bfloat16 hi = __float2bfloat16_rn(v);
    __nv_bfloat16 lo = __float2bfloat16_rn(v - __bfloat162float(hi));
    g_Whi[idx] = hi;
    g_Wlo[idx] = lo;
}

// ---------------- HMMA GEMM: out = A @ W^T(+b), bf16x3 split, fp32 acc ------
__device__ __forceinline__ void ldm4(uint32_t* d, uint32_t addr) {
    asm volatile("ldmatrix.sync.aligned.m8n8.x4.shared.b16 {%0,%1,%2,%3}, [%4];"
                 : "=r"(d[0]), "=r"(d[1]), "=r"(d[2]), "=r"(d[3]) : "r"(addr));
}

__device__ __forceinline__ void mma16816(float* c, const uint32_t* a,
                                         uint32_t b0, uint32_t b1) {
    asm volatile(
        "mma.sync.aligned.m16n8k16.row.col.f32.bf16.bf16.f32 "
        "{%0,%1,%2,%3}, {%4,%5,%6,%7}, {%8,%9}, {%0,%1,%2,%3};"
        : "+f"(c[0]), "+f"(c[1]), "+f"(c[2]), "+f"(c[3])
        : "r"(a[0]), "r"(a[1]), "r"(a[2]), "r"(a[3]), "r"(b0), "r"(b1));
}

__global__ void __launch_bounds__(256, 1) hmma_gemm(
        const float* __restrict__ A,
        const __nv_bfloat16* __restrict__ Whi, const __nv_bfloat16* __restrict__ Wlo,
        const float* __restrict__ bias, float* __restrict__ out, int n) {
    extern __shared__ __align__(16) char smem[];
    __nv_bfloat16* sAhi = (__nv_bfloat16*)smem;
    __nv_bfloat16* sAlo = sAhi + 128 * SAS;
    __nv_bfloat16* sBhi = sAlo + 128 * SAS;
    __nv_bfloat16* sBlo = sBhi + 128 * SAS;
    uint32_t uAhi = (uint32_t)__cvta_generic_to_shared(sAhi);
    uint32_t uAlo = (uint32_t)__cvta_generic_to_shared(sAlo);
    uint32_t uBhi = (uint32_t)__cvta_generic_to_shared(sBhi);
    uint32_t uBlo = (uint32_t)__cvta_generic_to_shared(sBlo);

    int tid = threadIdx.x, lane = tid & 31, wid = tid >> 5;
    int row0 = blockIdx.x * 128;

    // stage W hi/lo (bf16 [n][k], 16B chunks)
    for (int i = tid; i < 2048; i += 256) {
        int r = i >> 4, c = i & 15;
        *(uint4*)&sBhi[r * SAS + c * 8] = ((const uint4*)Whi)[i];
        *(uint4*)&sBlo[r * SAS + c * 8] = ((const uint4*)Wlo)[i];
    }
    // stage A: load fp32, split to bf16 hi/lo
    for (int i = tid; i < 4096; i += 256) {
        int r = i >> 5, c4 = (i & 31) * 4;
        int gr = row0 + r;
        float4 v = make_float4(0.f, 0.f, 0.f, 0.f);
        if (gr < n) v = *(const float4*)&A[(size_t)gr * F + c4];
        __nv_bfloat162 h01 = __floats2bfloat162_rn(v.x, v.y);
        __nv_bfloat162 h23 = __floats2bfloat162_rn(v.z, v.w);
        __nv_bfloat162 l01 = __floats2bfloat162_rn(v.x - __bfloat162float(h01.x),
                                                   v.y - __bfloat162float(h01.y));
        __nv_bfloat162 l23 = __floats2bfloat162_rn(v.z - __bfloat162float(h23.x),
                                                   v.w - __bfloat162float(h23.y));
        *(__nv_bfloat162*)&sAhi[r * SAS + c4]     = h01;
        *(__nv_bfloat162*)&sAhi[r * SAS + c4 + 2] = h23;
        *(__nv_bfloat162*)&sAlo[r * SAS + c4]     = l01;
        *(__nv_bfloat162*)&sAlo[r * SAS + c4 + 2] = l23;
    }
    __syncthreads();

    int wm = wid & 3, wn = wid >> 2;
    int m_base = wm * 32, n_base = wn * 64;

    float c[2][8][4];
#pragma unroll
    for (int i = 0; i < 2; i++)
#pragma unroll
        for (int j = 0; j < 8; j++)
#pragma unroll
            for (int q = 0; q < 4; q++) c[i][j][q] = 0.f;

    // A-frag lane addressing: row = m_base+i*16+(lane&15), col = k0+((lane>>4)*8)
    int a_r = lane & 15, a_c8 = (lane >> 4) << 3;
    // B-frag lane addressing: row = n_base+jp*16+((lane>>4)&1)*8+(lane&7),
    //                          col = k0+((lane>>3)&1)*8
    int b_r = (((lane >> 4) & 1) << 3) + (lane & 7), b_c8 = ((lane >> 3) & 1) << 3;

    for (int ks = 0; ks < 8; ks++) {
        int k0 = ks * 16;
        uint32_t ahi[2][4], alo[2][4];
#pragma unroll
        for (int i = 0; i < 2; i++) {
            uint32_t off = (uint32_t)((m_base + i * 16 + a_r) * SAS + k0 + a_c8) * 2;
            ldm4(ahi[i], uAhi + off);
            ldm4(alo[i], uAlo + off);
        }
#pragma unroll
        for (int jp = 0; jp < 4; jp++) {
            uint32_t off = (uint32_t)((n_base + jp * 16 + b_r) * SAS + k0 + b_c8) * 2;
            uint32_t bh[4], bl[4];
            ldm4(bh, uBhi + off);
            ldm4(bl, uBlo + off);
#pragma unroll
            for (int i = 0; i < 2; i++) {
                mma16816(c[i][2 * jp],     ahi[i], bh[0], bh[1]);
                mma16816(c[i][2 * jp],     alo[i], bh[0], bh[1]);
                mma16816(c[i][2 * jp],     ahi[i], bl[0], bl[1]);
                mma16816(c[i][2 * jp + 1], ahi[i], bh[2], bh[3]);
                mma16816(c[i][2 * jp + 1], alo[i], bh[2], bh[3]);
                mma16816(c[i][2 * jp + 1], ahi[i], bl[2], bl[3]);
            }
        }
    }

    // epilogue: D frag -> rows (t/4, t/4+8), cols 2*(t%4)+{0,1} per atom
    int qr = lane >> 2, qc = (lane & 3) * 2;
#pragma unroll
    for (int i = 0; i < 2; i++) {
#pragma unroll
        for (int j = 0; j < 8; j++) {
            int r0g = row0 + m_base + i * 16 + qr;
            int nn0 = n_base + j * 8 + qc;
            float2 bb = __ldg((const float2*)&bias[nn0]);
            if (r0g < n) {
                float2 o = make_float2(c[i][j][0] + bb.x, c[i][j][1] + bb.y);
                *(float2*)&out[(size_t)r0g * F + nn0] = o;
            }
            if (r0g + 8 < n) {
                float2 o = make_float2(c[i][j][2] + bb.x, c[i][j][3] + bb.y);
                *(float2*)&out[(size_t)(r0g + 8) * F + nn0] = o;
            }
        }
    }
}

// ---------------- fused gather: softmax-attention aggregate + epilogue --------
__device__ __forceinline__ float lrelu(float v) {
    return (v > 0.f) ? v : 0.2f * v;
}

__device__ __forceinline__ void proc_edge(float4 xl4, const float4& xr4,
                                          const float4& attv, int lane,
                                          float& d, float4& s) {
    float p = lrelu(xl4.x + xr4.x) * attv.x
            + lrelu(xl4.y + xr4.y) * attv.y
            + lrelu(xl4.z + xr4.z) * attv.z
            + lrelu(xl4.w + xr4.w) * attv.w;
    p += __shfl_xor_sync(0xffffffffu, p, 1);
    p += __shfl_xor_sync(0xffffffffu, p, 2);
    p += __shfl_xor_sync(0xffffffffu, p, 4);
    float w = 0.f;
    if ((lane & 7) == 0) w = __expf(p);
    w = __shfl_sync(0xffffffffu, w, lane & 24);
    d += w;
    s.x += w * xl4.x;
    s.y += w * xl4.y;
    s.z += w * xl4.z;
    s.w += w * xl4.w;
}

__global__ void __launch_bounds__(256) gat_gather(
        const float* __restrict__ att, const float* __restrict__ conv_b,
        const float* __restrict__ ln_g, const float* __restrict__ ln_b) {
    int node = (blockIdx.x * blockDim.x + threadIdx.x) >> 5;
    int lane = threadIdx.x & 31;
    if (node >= NN) return;
    int beg = g_rowptr[node];
    int end = g_rowptr[node + 1];

    float4 xr4 = *(const float4*)&g_xr[(size_t)node * F + lane * 4];
    float4 attv = __ldg((const float4*)&att[lane * 4]);

    float d = 0.f;
    float4 s = make_float4(0.f, 0.f, 0.f, 0.f);

    int e = beg;
    for (; e + 4 <= end; e += 4) {
        int s0 = g_csrsrc[e + 0];
        int s1 = g_csrsrc[e + 1];
        int s2 = g_csrsrc[e + 2];
        int s3 = g_csrsrc[e + 3];
        float4 a0 = __ldg((const float4*)&g_xl[(size_t)s0 * F + lane * 4]);
        float4 a1 = __ldg((const float4*)&g_xl[(size_t)s1 * F + lane * 4]);
        float4 a2 = __ldg((const float4*)&g_xl[(size_t)s2 * F + lane * 4]);
        float4 a3 = __ldg((const float4*)&g_xl[(size_t)s3 * F + lane * 4]);
        proc_edge(a0, xr4, attv, lane, d, s);
        proc_edge(a1, xr4, attv, lane, d, s);
        proc_edge(a2, xr4, attv, lane, d, s);
        proc_edge(a3, xr4, attv, lane, d, s);
    }
    for (; e < end; e++) {
        int s0 = g_csrsrc[e];
        float4 a0 = __ldg((const float4*)&g_xl[(size_t)s0 * F + lane * 4]);
        proc_edge(a0, xr4, attv, lane, d, s);
    }

    float invd = 1.0f / (d + 1e-16f);
    float4 cb = __ldg((const float4*)&conv_b[lane * 4]);
    float4 o;
    o.x = s.x * invd + cb.x;
    o.y = s.y * invd + cb.y;
    o.z = s.z * invd + cb.z;
    o.w = s.w * invd + cb.w;
    o.x = (o.x > 0.f) ? o.x : (__expf(o.x) - 1.f);
    o.y = (o.y > 0.f) ? o.y : (__expf(o.y) - 1.f);
    o.z = (o.z > 0.f) ? o.z : (__expf(o.z) - 1.f);
    o.w = (o.w > 0.f) ? o.w : (__expf(o.w) - 1.f);
    float4 res = *(const float4*)&g_h[(size_t)node * F + lane * 4];
    o.x += res.x; o.y += res.y; o.z += res.z; o.w += res.w;

    float sum = o.x + o.y + o.z + o.w;
#pragma unroll
    for (int off = 16; off; off >>= 1) sum += __shfl_xor_sync(0xffffffffu, sum, off);
    float mu = sum * (1.f / 128.f);
    float dx0 = o.x - mu, dx1 = o.y - mu, dx2 = o.z - mu, dx3 = o.w - mu;
    float sq = dx0 * dx0 + dx1 * dx1 + dx2 * dx2 + dx3 * dx3;
#pragma unroll
    for (int off = 16; off; off >>= 1) sq += __shfl_xor_sync(0xffffffffu, sq, off);
    float rstd = rsqrtf(sq * (1.f / 128.f) + 1e-5f);

    float4 lg = __ldg((const float4*)&ln_g[lane * 4]);
    float4 lb = __ldg((const float4*)&ln_b[lane * 4]);
    float4 w;
    w.x = dx0 * rstd * lg.x + lb.x;
    w.y = dx1 * rstd * lg.y + lb.y;
    w.z = dx2 * rstd * lg.z + lb.z;
    w.w = dx3 * rstd * lg.w + lb.w;
    *(float4*)&g_h[(size_t)node * F + lane * 4] = w;
}

// ---------------- pooling ----------------
__global__ void pool_zero() {
    int i = blockIdx.x * blockDim.x + threadIdx.x;
    if (i < NG * F) g_pool[i] = 0.f;
    if (i < NG) g_cnt[i] = 0.f;
}

__global__ void pool_accum() {
    int node = (blockIdx.x * blockDim.x + threadIdx.x) >> 5;
    int lane = threadIdx.x & 31;
    if (node >= NN) return;
    int g = g_batch32[node];
#pragma unroll
    for (int h = 0; h < HEADS; h++)
        atomicAdd(&g_pool[g * F + h * HD + lane],
                  g_h[(size_t)node * F + h * HD + lane]);
    if (lane == 0) atomicAdd(&g_cnt[g], 1.0f);
}

__global__ void pool_final(float* __restrict__ out) {
    int i = blockIdx.x * blockDim.x + threadIdx.x;
    if (i >= NG * F) return;
    out[i] = g_pool[i] / fmaxf(g_cnt[i >> 7], 1.0f);
}

// ---------------- launch ----------------
extern "C" void kernel_launch(void* const* d_in, const int* in_sizes, int n_in,
                              void* d_out, int out_size) {
    const float* x        = (const float*)d_in[0];
    const void*  ei_raw   = d_in[1];
    const void*  batch_raw= d_in[2];
    const float* emb_W    = (const float*)d_in[3];
    const float* emb_b    = (const float*)d_in[4];
    const float* lin_l_W  = (const float*)d_in[5];
    const float* lin_l_b  = (const float*)d_in[6];
    const float* lin_r_W  = (const float*)d_in[7];
    const float* lin_r_b  = (const float*)d_in[8];
    const float* att      = (const float*)d_in[9];
    const float* conv_b   = (const float*)d_in[10];
    const float* ln_g     = (const float*)d_in[11];
    const float* ln_b     = (const float*)d_in[12];
    float* out = (float*)d_out;

    float *p_h, *p_xl, *p_xr;
    int *p_ei, *p_batch;
    __nv_bfloat16 *p_Whi, *p_Wlo;
    cudaGetSymbolAddress((void**)&p_h, g_h);
    cudaGetSymbolAddress((void**)&p_xl, g_xl);
    cudaGetSymbolAddress((void**)&p_xr, g_xr);
    cudaGetSymbolAddress((void**)&p_ei, g_ei32);
    cudaGetSymbolAddress((void**)&p_batch, g_batch32);
    cudaGetSymbolAddress((void**)&p_Whi, g_Whi);
    cudaGetSymbolAddress((void**)&p_Wlo, g_Wlo);

    cudaFuncSetAttribute(hmma_gemm, cudaFuncAttributeMaxDynamicSharedMemorySize, SMEMSZ);

    const int ET_GRID = (NE + 255) / 256;
    const int NW_GRID = (NN + 7) / 8;

    // normalize index dtypes, then build dst-CSR once
    sniff_dtype<<<1, 1024>>>(ei_raw);
    convert_idx<<<(2 * NE + 255) / 256, 256>>>(ei_raw, p_ei, 2 * NE);
    convert_idx<<<(NN + 255) / 256, 256>>>(batch_raw, p_batch, NN);
    csr_count_zero<<<(NN + 255) / 256, 256>>>();
    csr_count<<<ET_GRID, 256>>>();
    csr_scan<<<1, 1024>>>();
    csr_fill<<<ET_GRID, 256>>>();

    // weight split (all 7 matrices, once)
    split_W_all<<<(7 * 16384 + 255) / 256, 256>>>(emb_W, lin_l_W, lin_r_W);

    // embedding GEMM
    hmma_gemm<<<TILES, 256, SMEMSZ>>>(x, p_Whi, p_Wlo, emb_b, p_h, NN);

    for (int l = 0; l < 3; l++) {
        hmma_gemm<<<TILES, 256, SMEMSZ>>>(p_h, p_Whi + (size_t)(1 + l) * 16384,
                                          p_Wlo + (size_t)(1 + l) * 16384,
                                          lin_l_b + (size_t)l * F, p_xl, NN);
        hmma_gemm<<<TILES, 256, SMEMSZ>>>(p_h, p_Whi + (size_t)(4 + l) * 16384,
                                          p_Wlo + (size_t)(4 + l) * 16384,
                                          lin_r_b + (size_t)l * F, p_xr, NN);
        gat_gather<<<NW_GRID, 256>>>(att + (size_t)l * F,
                                     conv_b + (size_t)l * F,
                                     ln_g + (size_t)l * F,
                                     ln_b + (size_t)l * F);
    }

    pool_zero<<<(NG * F + 255) / 256, 256>>>();
    pool_accum<<<NW_GRID, 256>>>();
    pool_final<<<(NG * F + 255) / 256, 256>>>(out);
}

// round 6
// speedup vs baseline: 2.7398x; 1.1203x over previous
#include <cuda_runtime.h>
#include <cuda_bf16.h>
#include <math.h>
#include <stdint.h>

#define NN 50000
#define NE 800000
#define F 128
#define HEADS 4
#define HD 32
#define NG 64
#define TILES64 ((NN + 63) / 64)   // 782
#define SAS 136                    // smem row stride in bf16 elems (272B: bank-safe)
// smem: A hi/lo 64 rows + B hi/lo 128 rows, stride SAS bf16
#define SMEMSZ ((2 * 64 + 2 * 128) * SAS * 2)   // 104448 bytes -> 2 CTAs/SM

// ---------------- static device scratch ----------------
__device__ __align__(16) float g_h[NN * F];
__device__ __align__(16) float g_xl[NN * F];
__device__ __align__(16) float g_xr[NN * F];
__device__ __align__(16) float g_pool[NG * F];
__device__ float g_cnt[NG];

__device__ int g_ei32[2 * NE];
__device__ int g_batch32[NN];
__device__ int g_is64;

// CSR by destination
__device__ int g_deg[NN];
__device__ int g_rowptr[NN + 1];
__device__ int g_cursor[NN];
__device__ int g_csrsrc[NE];

// 7 weight matrices bf16 hi/lo, transposed to [n][k] row-major:
// 0=emb, 1..3=lin_l, 4..6=lin_r
__device__ __align__(16) __nv_bfloat16 g_Whi[7 * 16384];
__device__ __align__(16) __nv_bfloat16 g_Wlo[7 * 16384];

// ---------------- dtype sniff ----------------
__global__ void sniff_dtype(const void* ei) {
    __shared__ int nz;
    if (threadIdx.x == 0) nz = 0;
    __syncthreads();
    const int* p = (const int*)ei;
    if (p[2 * threadIdx.x + 1] != 0) atomicOr(&nz, 1);
    __syncthreads();
    if (threadIdx.x == 0) g_is64 = (nz == 0) ? 1 : 0;
}

__global__ void convert_idx(const void* src, int* dst, int n) {
    int i = blockIdx.x * blockDim.x + threadIdx.x;
    if (i >= n) return;
    if (g_is64) dst[i] = (int)((const long long*)src)[i];
    else        dst[i] = ((const int*)src)[i];
}

// ---------------- CSR build (convert + count fused) ----------------
__global__ void csr_count_zero() {
    int i = blockIdx.x * blockDim.x + threadIdx.x;
    if (i < NN) g_deg[i] = 0;
}

// converts both src and dst halves of edge_index AND counts dst degrees
__global__ void convert_count(const void* ei) {
    int e = blockIdx.x * blockDim.x + threadIdx.x;
    if (e >= NE) return;
    int s, d;
    if (g_is64) {
        s = (int)((const long long*)ei)[e];
        d = (int)((const long long*)ei)[NE + e];
    } else {
        s = ((const int*)ei)[e];
        d = ((const int*)ei)[NE + e];
    }
    g_ei32[e] = s;
    g_ei32[NE + e] = d;
    atomicAdd(&g_deg[d], 1);
}

__global__ void csr_scan() {
    __shared__ int wsum[32];
    __shared__ int carry_s;
    int tid = threadIdx.x, lane = tid & 31, wid = tid >> 5;
    if (tid == 0) carry_s = 0;
    __syncthreads();
    for (int base = 0; base < NN; base += 1024) {
        int i = base + tid;
        int v = (i < NN) ? g_deg[i] : 0;
        int x = v;
#pragma unroll
        for (int off = 1; off < 32; off <<= 1) {
            int y = __shfl_up_sync(0xffffffffu, x, off);
            if (lane >= off) x += y;
        }
        if (lane == 31) wsum[wid] = x;
        __syncthreads();
        if (wid == 0) {
            int y = wsum[lane];
#pragma unroll
            for (int off = 1; off < 32; off <<= 1) {
                int z = __shfl_up_sync(0xffffffffu, y, off);
                if (lane >= off) y += z;
            }
            wsum[lane] = y;
        }
        __syncthreads();
        int carry = carry_s;
        int excl = x - v + (wid > 0 ? wsum[wid - 1] : 0) + carry;
        if (i < NN) { g_rowptr[i] = excl; g_cursor[i] = excl; }
        int total = wsum[31];
        __syncthreads();
        if (tid == 0) carry_s = carry + total;
        __syncthreads();
    }
    if (threadIdx.x == 0) g_rowptr[NN] = carry_s;
}

__global__ void csr_fill() {
    int e = blockIdx.x * blockDim.x + threadIdx.x;
    if (e >= NE) return;
    int src = g_ei32[e];
    int dst = g_ei32[NE + e];
    int pos = atomicAdd(&g_cursor[dst], 1);
    g_csrsrc[pos] = src;
}

// ---------------- bf16 split of W (transposed to [n][k]) --------------------
__global__ void split_W_all(const float* __restrict__ emb_W,
                            const float* __restrict__ llW,
                            const float* __restrict__ lrW) {
    int idx = blockIdx.x * blockDim.x + threadIdx.x;
    if (idx >= 7 * 16384) return;
    int w = idx >> 14, e = idx & 16383;
    int nrow = e >> 7, k = e & 127;
    float v;
    if (w == 0)      v = emb_W[k * F + nrow];
    else if (w < 4)  v = llW[(size_t)(w - 1) * F * F + k * F + nrow];
    else             v = lrW[(size_t)(w - 4) * F * F + k * F + nrow];
    __nv_bfloat16 hi = __float2bfloat16_rn(v);
    __nv_bfloat16 lo = __float2bfloat16_rn(v - __bfloat162float(hi));
    g_Whi[idx] = hi;
    g_Wlo[idx] = lo;
}

// ---------------- HMMA GEMM: out = A @ W^T(+b), bf16x3 split, fp32 acc ------
// 64-row tiles, 2 CTAs/SM (104KB smem) so staging overlaps compute.
__device__ __forceinline__ void ldm4(uint32_t* d, uint32_t addr) {
    asm volatile("ldmatrix.sync.aligned.m8n8.x4.shared.b16 {%0,%1,%2,%3}, [%4];"
                 : "=r"(d[0]), "=r"(d[1]), "=r"(d[2]), "=r"(d[3]) : "r"(addr));
}

__device__ __forceinline__ void mma16816(float* c, const uint32_t* a,
                                         uint32_t b0, uint32_t b1) {
    asm volatile(
        "mma.sync.aligned.m16n8k16.row.col.f32.bf16.bf16.f32 "
        "{%0,%1,%2,%3}, {%4,%5,%6,%7}, {%8,%9}, {%0,%1,%2,%3};"
        : "+f"(c[0]), "+f"(c[1]), "+f"(c[2]), "+f"(c[3])
        : "r"(a[0]), "r"(a[1]), "r"(a[2]), "r"(a[3]), "r"(b0), "r"(b1));
}

__global__ void __launch_bounds__(256, 2) hmma_gemm(
        const float* __restrict__ A,
        const __nv_bfloat16* __restrict__ Whi, const __nv_bfloat16* __restrict__ Wlo,
        const float* __restrict__ bias, float* __restrict__ out, int n) {
    extern __shared__ __align__(16) char smem[];
    __nv_bfloat16* sAhi = (__nv_bfloat16*)smem;
    __nv_bfloat16* sAlo = sAhi + 64 * SAS;
    __nv_bfloat16* sBhi = sAlo + 64 * SAS;
    __nv_bfloat16* sBlo = sBhi + 128 * SAS;
    uint32_t uAhi = (uint32_t)__cvta_generic_to_shared(sAhi);
    uint32_t uAlo = (uint32_t)__cvta_generic_to_shared(sAlo);
    uint32_t uBhi = (uint32_t)__cvta_generic_to_shared(sBhi);
    uint32_t uBlo = (uint32_t)__cvta_generic_to_shared(sBlo);

    int tid = threadIdx.x, lane = tid & 31, wid = tid >> 5;
    int row0 = blockIdx.x * 64;

    // stage W hi/lo (bf16 [n][k] 128x128, 16B chunks)
    for (int i = tid; i < 2048; i += 256) {
        int r = i >> 4, c = i & 15;
        *(uint4*)&sBhi[r * SAS + c * 8] = ((const uint4*)Whi)[i];
        *(uint4*)&sBlo[r * SAS + c * 8] = ((const uint4*)Wlo)[i];
    }
    // stage A (64 rows): load fp32, split to bf16 hi/lo
    for (int i = tid; i < 2048; i += 256) {
        int r = i >> 5, c4 = (i & 31) * 4;
        int gr = row0 + r;
        float4 v = make_float4(0.f, 0.f, 0.f, 0.f);
        if (gr < n) v = *(const float4*)&A[(size_t)gr * F + c4];
        __nv_bfloat162 h01 = __floats2bfloat162_rn(v.x, v.y);
        __nv_bfloat162 h23 = __floats2bfloat162_rn(v.z, v.w);
        __nv_bfloat162 l01 = __floats2bfloat162_rn(v.x - __bfloat162float(h01.x),
                                                   v.y - __bfloat162float(h01.y));
        __nv_bfloat162 l23 = __floats2bfloat162_rn(v.z - __bfloat162float(h23.x),
                                                   v.w - __bfloat162float(h23.y));
        *(__nv_bfloat162*)&sAhi[r * SAS + c4]     = h01;
        *(__nv_bfloat162*)&sAhi[r * SAS + c4 + 2] = h23;
        *(__nv_bfloat162*)&sAlo[r * SAS + c4]     = l01;
        *(__nv_bfloat162*)&sAlo[r * SAS + c4 + 2] = l23;
    }
    __syncthreads();

    // warp tile 32x32: wm in {0,1} (M), wn in {0..3} (N)
    int wm = wid & 1, wn = wid >> 1;
    int m_base = wm * 32, n_base = wn * 32;

    float c[2][4][4];
#pragma unroll
    for (int i = 0; i < 2; i++)
#pragma unroll
        for (int j = 0; j < 4; j++)
#pragma unroll
            for (int q = 0; q < 4; q++) c[i][j][q] = 0.f;

    int a_r = lane & 15, a_c8 = (lane >> 4) << 3;
    int b_r = (((lane >> 4) & 1) << 3) + (lane & 7), b_c8 = ((lane >> 3) & 1) << 3;

#pragma unroll
    for (int ks = 0; ks < 8; ks++) {
        int k0 = ks * 16;
        uint32_t ahi[2][4], alo[2][4];
#pragma unroll
        for (int i = 0; i < 2; i++) {
            uint32_t off = (uint32_t)((m_base + i * 16 + a_r) * SAS + k0 + a_c8) * 2;
            ldm4(ahi[i], uAhi + off);
            ldm4(alo[i], uAlo + off);
        }
#pragma unroll
        for (int jp = 0; jp < 2; jp++) {
            uint32_t off = (uint32_t)((n_base + jp * 16 + b_r) * SAS + k0 + b_c8) * 2;
            uint32_t bh[4], bl[4];
            ldm4(bh, uBhi + off);
            ldm4(bl, uBlo + off);
#pragma unroll
            for (int i = 0; i < 2; i++) {
                mma16816(c[i][2 * jp],     ahi[i], bh[0], bh[1]);
                mma16816(c[i][2 * jp],     alo[i], bh[0], bh[1]);
                mma16816(c[i][2 * jp],     ahi[i], bl[0], bl[1]);
                mma16816(c[i][2 * jp + 1], ahi[i], bh[2], bh[3]);
                mma16816(c[i][2 * jp + 1], alo[i], bh[2], bh[3]);
                mma16816(c[i][2 * jp + 1], ahi[i], bl[2], bl[3]);
            }
        }
    }

    // epilogue: D frag lane mapping rows (lane>>2, +8), cols 2*(lane&3)+{0,1}
    int qr = lane >> 2, qc = (lane & 3) * 2;
#pragma unroll
    for (int i = 0; i < 2; i++) {
#pragma unroll
        for (int j = 0; j < 4; j++) {
            int r0g = row0 + m_base + i * 16 + qr;
            int nn0 = n_base + j * 8 + qc;
            float2 bb = __ldg((const float2*)&bias[nn0]);
            if (r0g < n) {
                float2 o = make_float2(c[i][j][0] + bb.x, c[i][j][1] + bb.y);
                *(float2*)&out[(size_t)r0g * F + nn0] = o;
            }
            if (r0g + 8 < n) {
                float2 o = make_float2(c[i][j][2] + bb.x, c[i][j][3] + bb.y);
                *(float2*)&out[(size_t)(r0g + 8) * F + nn0] = o;
            }
        }
    }
}

// ---------------- fused gather: softmax-attention aggregate + epilogue --------
__device__ __forceinline__ float lrelu(float v) {
    return (v > 0.f) ? v : 0.2f * v;
}

__device__ __forceinline__ void proc_edge(float4 xl4, const float4& xr4,
                                          const float4& attv, int lane,
                                          float& d, float4& s) {
    float p = lrelu(xl4.x + xr4.x) * attv.x
            + lrelu(xl4.y + xr4.y) * attv.y
            + lrelu(xl4.z + xr4.z) * attv.z
            + lrelu(xl4.w + xr4.w) * attv.w;
    p += __shfl_xor_sync(0xffffffffu, p, 1);
    p += __shfl_xor_sync(0xffffffffu, p, 2);
    p += __shfl_xor_sync(0xffffffffu, p, 4);
    float w = 0.f;
    if ((lane & 7) == 0) w = __expf(p);
    w = __shfl_sync(0xffffffffu, w, lane & 24);
    d += w;
    s.x += w * xl4.x;
    s.y += w * xl4.y;
    s.z += w * xl4.z;
    s.w += w * xl4.w;
}

__global__ void __launch_bounds__(256) gat_gather(
        const float* __restrict__ att, const float* __restrict__ conv_b,
        const float* __restrict__ ln_g, const float* __restrict__ ln_b) {
    int node = (blockIdx.x * blockDim.x + threadIdx.x) >> 5;
    int lane = threadIdx.x & 31;
    if (node >= NN) return;
    int beg = g_rowptr[node];
    int end = g_rowptr[node + 1];

    float4 xr4 = *(const float4*)&g_xr[(size_t)node * F + lane * 4];
    float4 attv = __ldg((const float4*)&att[lane * 4]);

    float d = 0.f;
    float4 s = make_float4(0.f, 0.f, 0.f, 0.f);

    int e = beg;
    for (; e + 4 <= end; e += 4) {
        int s0 = g_csrsrc[e + 0];
        int s1 = g_csrsrc[e + 1];
        int s2 = g_csrsrc[e + 2];
        int s3 = g_csrsrc[e + 3];
        float4 a0 = __ldg((const float4*)&g_xl[(size_t)s0 * F + lane * 4]);
        float4 a1 = __ldg((const float4*)&g_xl[(size_t)s1 * F + lane * 4]);
        float4 a2 = __ldg((const float4*)&g_xl[(size_t)s2 * F + lane * 4]);
        float4 a3 = __ldg((const float4*)&g_xl[(size_t)s3 * F + lane * 4]);
        proc_edge(a0, xr4, attv, lane, d, s);
        proc_edge(a1, xr4, attv, lane, d, s);
        proc_edge(a2, xr4, attv, lane, d, s);
        proc_edge(a3, xr4, attv, lane, d, s);
    }
    for (; e < end; e++) {
        int s0 = g_csrsrc[e];
        float4 a0 = __ldg((const float4*)&g_xl[(size_t)s0 * F + lane * 4]);
        proc_edge(a0, xr4, attv, lane, d, s);
    }

    float invd = 1.0f / (d + 1e-16f);
    float4 cb = __ldg((const float4*)&conv_b[lane * 4]);
    float4 o;
    o.x = s.x * invd + cb.x;
    o.y = s.y * invd + cb.y;
    o.z = s.z * invd + cb.z;
    o.w = s.w * invd + cb.w;
    o.x = (o.x > 0.f) ? o.x : (__expf(o.x) - 1.f);
    o.y = (o.y > 0.f) ? o.y : (__expf(o.y) - 1.f);
    o.z = (o.z > 0.f) ? o.z : (__expf(o.z) - 1.f);
    o.w = (o.w > 0.f) ? o.w : (__expf(o.w) - 1.f);
    float4 res = *(const float4*)&g_h[(size_t)node * F + lane * 4];
    o.x += res.x; o.y += res.y; o.z += res.z; o.w += res.w;

    float sum = o.x + o.y + o.z + o.w;
#pragma unroll
    for (int off = 16; off; off >>= 1) sum += __shfl_xor_sync(0xffffffffu, sum, off);
    float mu = sum * (1.f / 128.f);
    float dx0 = o.x - mu, dx1 = o.y - mu, dx2 = o.z - mu, dx3 = o.w - mu;
    float sq = dx0 * dx0 + dx1 * dx1 + dx2 * dx2 + dx3 * dx3;
#pragma unroll
    for (int off = 16; off; off >>= 1) sq += __shfl_xor_sync(0xffffffffu, sq, off);
    float rstd = rsqrtf(sq * (1.f / 128.f) + 1e-5f);

    float4 lg = __ldg((const float4*)&ln_g[lane * 4]);
    float4 lb = __ldg((const float4*)&ln_b[lane * 4]);
    float4 w;
    w.x = dx0 * rstd * lg.x + lb.x;
    w.y = dx1 * rstd * lg.y + lb.y;
    w.z = dx2 * rstd * lg.z + lb.z;
    w.w = dx3 * rstd * lg.w + lb.w;
    *(float4*)&g_h[(size_t)node * F + lane * 4] = w;
}

// ---------------- pooling ----------------
__global__ void pool_zero() {
    int i = blockIdx.x * blockDim.x + threadIdx.x;
    if (i < NG * F) g_pool[i] = 0.f;
    if (i < NG) g_cnt[i] = 0.f;
}

__global__ void pool_accum() {
    int node = (blockIdx.x * blockDim.x + threadIdx.x) >> 5;
    int lane = threadIdx.x & 31;
    if (node >= NN) return;
    int g = g_batch32[node];
#pragma unroll
    for (int h = 0; h < HEADS; h++)
        atomicAdd(&g_pool[g * F + h * HD + lane],
                  g_h[(size_t)node * F + h * HD + lane]);
    if (lane == 0) atomicAdd(&g_cnt[g], 1.0f);
}

__global__ void pool_final(float* __restrict__ out) {
    int i = blockIdx.x * blockDim.x + threadIdx.x;
    if (i >= NG * F) return;
    out[i] = g_pool[i] / fmaxf(g_cnt[i >> 7], 1.0f);
}

// ---------------- launch ----------------
extern "C" void kernel_launch(void* const* d_in, const int* in_sizes, int n_in,
                              void* d_out, int out_size) {
    const float* x        = (const float*)d_in[0];
    const void*  ei_raw   = d_in[1];
    const void*  batch_raw= d_in[2];
    const float* emb_W    = (const float*)d_in[3];
    const float* emb_b    = (const float*)d_in[4];
    const float* lin_l_W  = (const float*)d_in[5];
    const float* lin_l_b  = (const float*)d_in[6];
    const float* lin_r_W  = (const float*)d_in[7];
    const float* lin_r_b  = (const float*)d_in[8];
    const float* att      = (const float*)d_in[9];
    const float* conv_b   = (const float*)d_in[10];
    const float* ln_g     = (const float*)d_in[11];
    const float* ln_b     = (const float*)d_in[12];
    float* out = (float*)d_out;

    float *p_h, *p_xl, *p_xr;
    int *p_batch;
    __nv_bfloat16 *p_Whi, *p_Wlo;
    cudaGetSymbolAddress((void**)&p_h, g_h);
    cudaGetSymbolAddress((void**)&p_xl, g_xl);
    cudaGetSymbolAddress((void**)&p_xr, g_xr);
    cudaGetSymbolAddress((void**)&p_batch, g_batch32);
    cudaGetSymbolAddress((void**)&p_Whi, g_Whi);
    cudaGetSymbolAddress((void**)&p_Wlo, g_Wlo);

    cudaFuncSetAttribute(hmma_gemm, cudaFuncAttributeMaxDynamicSharedMemorySize, SMEMSZ);

    const int ET_GRID = (NE + 255) / 256;
    const int NW_GRID = (NN + 7) / 8;

    // normalize index dtypes + build dst-CSR once
    sniff_dtype<<<1, 1024>>>(ei_raw);
    csr_count_zero<<<(NN + 255) / 256, 256>>>();
    convert_count<<<ET_GRID, 256>>>(ei_raw);
    convert_idx<<<(NN + 255) / 256, 256>>>(batch_raw, p_batch, NN);
    csr_scan<<<1, 1024>>>();
    csr_fill<<<ET_GRID, 256>>>();

    // weight split (all 7 matrices, once)
    split_W_all<<<(7 * 16384 + 255) / 256, 256>>>(emb_W, lin_l_W, lin_r_W);

    // embedding GEMM
    hmma_gemm<<<TILES64, 256, SMEMSZ>>>(x, p_Whi, p_Wlo, emb_b, p_h, NN);

    for (int l = 0; l < 3; l++) {
        hmma_gemm<<<TILES64, 256, SMEMSZ>>>(p_h, p_Whi + (size_t)(1 + l) * 16384,
                                            p_Wlo + (size_t)(1 + l) * 16384,
                                            lin_l_b + (size_t)l * F, p_xl, NN);
        hmma_gemm<<<TILES64, 256, SMEMSZ>>>(p_h, p_Whi + (size_t)(4 + l) * 16384,
                                            p_Wlo + (size_t)(4 + l) * 16384,
                                            lin_r_b + (size_t)l * F, p_xr, NN);
        gat_gather<<<NW_GRID, 256>>>(att + (size_t)l * F,
                                     conv_b + (size_t)l * F,
                                     ln_g + (size_t)l * F,
                                     ln_b + (size_t)l * F);
    }

    pool_zero<<<(NG * F + 255) / 256, 256>>>();
    pool_accum<<<NW_GRID, 256>>>();
    pool_final<<<(NG * F + 255) / 256, 256>>>(out);
}